// round 16
// baseline (speedup 1.0000x reference)
#include <cuda_runtime.h>
#include <cuda_bf16.h>
#include <cuda_fp16.h>
#include <cstdint>

// ---------------------------------------------------------------------------
// EarlyFusionGRU: two biGRUs (B=256, T=512, H=128) + fusion MLP + 2 heads.
// Backward direction contributes only hb_seq[0] = ONE GRU step from h0=0 on
// x[:, T-1]. R16: NB=4 fused kernel with tensor/activation pipe split —
// warps 0-11 run h-MMAs(t) then x-MMAs(t+1) back-to-back (tensor pipe never
// idles); warps 12-15 stage+convert x and run the ENTIRE activation in the
// shadow of the x-MMA phase (named-barrier handoff).
// ---------------------------------------------------------------------------

#define B 256
#define T 512
#define H 128
#define G3 384   // 3*H
#define BPITCH 136   // h B-tile row pitch
#define NB 4         // batches per CTA

static __device__ float d_hcat[(size_t)B * 512];      // [hg_f | hg_b | ha_f | ha_b]

__device__ __forceinline__ float sigmoidf_(float x) { return 1.0f / (1.0f + expf(-x)); }
__device__ __forceinline__ float tanh_ap(float x) {
    float y; asm("tanh.approx.f32 %0, %1;" : "=f"(y) : "f"(x)); return y;
}
__device__ __forceinline__ float sig_ap(float x) {
    return fmaf(tanh_ap(0.5f * x), 0.5f, 0.5f);
}
__device__ __forceinline__ uint32_t pkh2(float a, float b) {
    __half2 h = __floats2half2_rn(a, b);
    return *(uint32_t*)&h;
}
__device__ __forceinline__ void mma16816(float* c, const uint32_t* a, uint32_t b0, uint32_t b1) {
    asm volatile(
        "mma.sync.aligned.m16n8k16.row.col.f32.f16.f16.f32 "
        "{%0,%1,%2,%3}, {%4,%5,%6,%7}, {%8,%9}, {%0,%1,%2,%3};"
        : "+f"(c[0]), "+f"(c[1]), "+f"(c[2]), "+f"(c[3])
        : "r"(a[0]), "r"(a[1]), "r"(a[2]), "r"(a[3]), "r"(b0), "r"(b1));
}
__device__ __forceinline__ uint32_t smem_u32(const void* p) {
    uint32_t a; asm("{ .reg .u64 t; cvta.to.shared.u64 t, %1; cvt.u32.u64 %0, t; }" : "=r"(a) : "l"(p));
    return a;
}
__device__ __forceinline__ void cpasync4(uint32_t dst, const void* src) {
    asm volatile("cp.async.ca.shared.global [%0], [%1], 4;" :: "r"(dst), "l"(src));
}
#define CP_COMMIT() asm volatile("cp.async.commit_group;" ::: "memory")
#define CP_WAIT1()  asm volatile("cp.async.wait_group 1;" ::: "memory")
#define CP_WAIT0()  asm volatile("cp.async.wait_group 0;" ::: "memory")
#define BAR2_ARRIVE() asm volatile("bar.arrive 2, 512;" ::: "memory")
#define BAR2_SYNC()   asm volatile("bar.sync 2, 512;" ::: "memory")

// ---- fused recurrence + shadowed projection/activation ----------------------
__global__ __launch_bounds__(512, 1) void rec_fused_kernel(
    const float* __restrict__ g_x, const float* __restrict__ a_x,
    const float* __restrict__ g_wif, const float* __restrict__ g_bif,
    const float* __restrict__ g_whf, const float* __restrict__ g_bhf,
    const float* __restrict__ a_wif, const float* __restrict__ a_bif,
    const float* __restrict__ a_whf, const float* __restrict__ a_bhf) {
    int net = blockIdx.y;
    int b0 = blockIdx.x * NB;
    const float* x  = net ? a_x : g_x;
    int I           = net ? 64 : 63;
    const float* Wi = net ? a_wif : g_wif;
    const float* bi = net ? a_bif : g_bif;
    const float* Wh = net ? a_whf : g_whf;
    const float* bh = net ? a_bhf : g_bhf;

    int tid = threadIdx.x;
    int wid = tid >> 5;
    int lane = tid & 31;
    int qr = lane >> 2;
    int qc = lane & 3;

    // smem: Bh | Bx[2] | Dsh | xg[2] | slab[2] | XFs
    extern __shared__ char dynsm[];
    __half (*Bh)[BPITCH]   = (__half(*)[BPITCH])dynsm;                 // 2176 -> 2304
    __half (*Bx)[8][72]    = (__half(*)[8][72])(dynsm + 2304);         // 2304
    float (*Dsh)[10]       = (float(*)[10])(dynsm + 4608);             // 15360
    float (*xg)[384][10]   = (float(*)[384][10])(dynsm + 19968);       // 30720
    float* slab            = (float*)(dynsm + 50688);                  // 2048
    uint4* XFs             = (uint4*)(dynsm + 52736);                  // 49152
    uint32_t slab_u32 = smem_u32(slab);

    // ---- Wh fragments in registers (only loop-live frag array) -------------
    uint32_t A[2][8][4];
    if (wid < 12) {
#pragma unroll
        for (int mt = 0; mt < 2; mt++) {
            int R = (wid * 2 + mt) * 16;
            int r0 = R + qr, r1 = r0 + 8;
            const float2* w0p = (const float2*)(Wh + (size_t)r0 * 128);
            const float2* w1p = (const float2*)(Wh + (size_t)r1 * 128);
#pragma unroll
            for (int kb = 0; kb < 8; kb++) {
                int ci = kb * 8 + qc;
                float2 e00 = w0p[ci], e10 = w1p[ci];
                float2 e01 = w0p[ci + 4], e11 = w1p[ci + 4];
                A[mt][kb][0] = pkh2(e00.x, e00.y);
                A[mt][kb][1] = pkh2(e10.x, e10.y);
                A[mt][kb][2] = pkh2(e01.x, e01.y);
                A[mt][kb][3] = pkh2(e11.x, e11.y);
            }
            // Wi fragments -> SMEM private slots
#pragma unroll
            for (int kx = 0; kx < 4; kx++) {
                int k0 = kx * 16 + qc * 2;
                uint32_t f[4];
#pragma unroll
                for (int r = 0; r < 2; r++) {
                    int ka = k0 + r * 8, kb2 = ka + 1;
                    float wa0 = (ka < I) ? Wi[(size_t)r0 * I + ka] : 0.0f;
                    float wa1 = (kb2 < I) ? Wi[(size_t)r0 * I + kb2] : 0.0f;
                    float wb0 = (ka < I) ? Wi[(size_t)r1 * I + ka] : 0.0f;
                    float wb1 = (kb2 < I) ? Wi[(size_t)r1 * I + kb2] : 0.0f;
                    f[0 + r * 2] = pkh2(wa0, wa1);
                    f[1 + r * 2] = pkh2(wb0, wb1);
                }
                XFs[(mt * 4 + kx) * 384 + tid] = make_uint4(f[0], f[1], f[2], f[3]);
            }
        }
    }

    // zero B-tiles (h0 = 0; batch rows NB..7 and pad cols stay zero forever)
    for (int i = tid; i < 8 * BPITCH; i += 512)
        ((__half*)Bh)[i] = __float2half_rn(0.0f);
    for (int i = tid; i < 2 * 8 * 72; i += 512)
        ((__half*)Bx)[i] = __float2half_rn(0.0f);

    // act-warp state (warps 12-15): thread pt owns jj = pt, batches 0..3
    int pt = tid - 384;                 // valid when wid >= 12
    float brz_r = 0.f, brz_z = 0.f, bin = 0.f, bhn = 0.f;
    float hreg[NB];
#pragma unroll
    for (int b = 0; b < NB; b++) hreg[b] = 0.0f;
    if (wid >= 12) {
        brz_r = bi[pt] + bh[pt];
        brz_z = bi[128 + pt] + bh[128 + pt];
        bin   = bi[256 + pt];
        bhn   = bh[256 + pt];
    }
    __syncthreads();

    // ---- prologue -----------------------------------------------------------
    if (wid >= 12) {
        // stage slab[0]<-x(0), slab[1]<-x(1)
#pragma unroll 1
        for (int tt = 0; tt < 2; tt++) {
            for (int i = pt; i < 256; i += 128) {
                int b = i >> 6, k = i & 63;
                if (k < I)
                    cpasync4(slab_u32 + (tt * 256 + i) * 4,
                             x + (size_t)(b0 + b) * (T * I) + (size_t)tt * I + k);
            }
            CP_COMMIT();
        }
        CP_WAIT0();
        // convert Bx[0]<-x(0), Bx[1]<-x(1)
        for (int i = pt; i < 512; i += 128) {
            int buf = i >> 8, r = (i >> 6) & 3, k = i & 63;
            float v = (k < I) ? slab[buf * 256 + r * 64 + k] : 0.0f;
            Bx[buf][r][k] = __float2half_rn(v);
        }
        // stage slab[0] <- x(2)
        for (int i = pt; i < 256; i += 128) {
            int b = i >> 6, k = i & 63;
            if (k < I)
                cpasync4(slab_u32 + i * 4,
                         x + (size_t)(b0 + b) * (T * I) + (size_t)2 * I + k);
        }
        CP_COMMIT();
    }
    __syncthreads();
    // xg[0] = Wi @ x(0)
    if (wid < 12) {
        const __half* BxF = &Bx[0][0][0];
#pragma unroll
        for (int mt = 0; mt < 2; mt++) {
            float c[4] = {0.f, 0.f, 0.f, 0.f};
#pragma unroll
            for (int kx = 0; kx < 4; kx++) {
                int koff = qr * 72 + kx * 16 + qc * 2;
                uint32_t bf0 = *(const uint32_t*)(BxF + koff);
                uint32_t bf1 = *(const uint32_t*)(BxF + koff + 8);
                uint4 f = XFs[(mt * 4 + kx) * 384 + tid];
                uint32_t af[4] = {f.x, f.y, f.z, f.w};
                mma16816(c, af, bf0, bf1);
            }
            int R = (wid * 2 + mt) * 16;
            *(float2*)&xg[0][R + qr][2 * qc]     = make_float2(c[0], c[1]);
            *(float2*)&xg[0][R + qr + 8][2 * qc] = make_float2(c[2], c[3]);
        }
    }
    __syncthreads();

    const __half* BhF = &Bh[0][0];

#pragma unroll 1
    for (int t = 0; t < T; t++) {
        if (wid < 12) {
            // ---- h-MMAs(t): uniform over all 24 m-tiles ---------------------
            float c0[2][4], c1[2][4];
#pragma unroll
            for (int mt = 0; mt < 2; mt++)
#pragma unroll
                for (int r = 0; r < 4; r++) { c0[mt][r] = 0.0f; c1[mt][r] = 0.0f; }
#pragma unroll
            for (int kb = 0; kb < 8; kb += 2) {
                int koff = qr * BPITCH + kb * 16 + qc * 2;
                uint32_t bf0 = *(const uint32_t*)(BhF + koff);
                uint32_t bf1 = *(const uint32_t*)(BhF + koff + 8);
                uint32_t bf2 = *(const uint32_t*)(BhF + koff + 16);
                uint32_t bf3 = *(const uint32_t*)(BhF + koff + 24);
#pragma unroll
                for (int mt = 0; mt < 2; mt++) {
                    mma16816(c0[mt], A[mt][kb], bf0, bf1);
                    mma16816(c1[mt], A[mt][kb + 1], bf2, bf3);
                }
            }
#pragma unroll
            for (int mt = 0; mt < 2; mt++) {
                int R = (wid * 2 + mt) * 16;
                *(float2*)&Dsh[R + qr][2 * qc] =
                    make_float2(c0[mt][0] + c1[mt][0], c0[mt][1] + c1[mt][1]);
                *(float2*)&Dsh[R + qr + 8][2 * qc] =
                    make_float2(c0[mt][2] + c1[mt][2], c0[mt][3] + c1[mt][3]);
            }
            BAR2_ARRIVE();      // hand Dsh(t) to the act warps

            // ---- x-MMAs for step t+1 (reads Bx[(t+1)&1]) --------------------
            const __half* BxF = &Bx[(t + 1) & 1][0][0];
#pragma unroll
            for (int mt = 0; mt < 2; mt++) {
                float c[4] = {0.f, 0.f, 0.f, 0.f};
#pragma unroll
                for (int kx = 0; kx < 4; kx++) {
                    int koff = qr * 72 + kx * 16 + qc * 2;
                    uint32_t bf0 = *(const uint32_t*)(BxF + koff);
                    uint32_t bf1 = *(const uint32_t*)(BxF + koff + 8);
                    uint4 f = XFs[(mt * 4 + kx) * 384 + tid];
                    uint32_t af[4] = {f.x, f.y, f.z, f.w};
                    mma16816(c, af, bf0, bf1);
                }
                int R = (wid * 2 + mt) * 16;
                int nb = (t + 1) & 1;
                *(float2*)&xg[nb][R + qr][2 * qc]     = make_float2(c[0], c[1]);
                *(float2*)&xg[nb][R + qr + 8][2 * qc] = make_float2(c[2], c[3]);
            }
        } else {
            // ---- stage slab x(t+3) into slab[(t+1)&1] -----------------------
            int tn = (t + 3 < T) ? (t + 3) : (T - 1);
            uint32_t dst = slab_u32 + (((t + 1) & 1) * 256) * 4;
            for (int i = pt; i < 256; i += 128) {
                int b = i >> 6, k = i & 63;
                if (k < I)
                    cpasync4(dst + i * 4,
                             x + (size_t)(b0 + b) * (T * I) + (size_t)tn * I + k);
            }
            CP_COMMIT();
            CP_WAIT1();          // slab[t&1] = x(t+2) resident
            // convert Bx[t&1] <- x(t+2)
            for (int i = pt; i < 256; i += 128) {
                int r = i >> 6, k = i & 63;
                float v = (k < I) ? slab[(t & 1) * 256 + r * 64 + k] : 0.0f;
                Bx[t & 1][r][k] = __float2half_rn(v);
            }
            BAR2_SYNC();         // wait for Dsh(t)

            // ---- activation(t): 4 entries per thread (jj = pt) --------------
            const float (*xgc)[10] = xg[t & 1];
#pragma unroll
            for (int b = 0; b < NB; b++) {
                float r = sig_ap(xgc[pt][b] + Dsh[pt][b] + brz_r);
                float z = sig_ap(xgc[128 + pt][b] + Dsh[128 + pt][b] + brz_z);
                float n = tanh_ap(xgc[256 + pt][b] + bin + r * (Dsh[256 + pt][b] + bhn));
                hreg[b] = n + z * (hreg[b] - n);
                Bh[b][pt] = __float2half_rn(hreg[b]);
            }
        }
        __syncthreads();   // Bh(t+1), xg[(t+1)&1], Bx consistency
    }

    // write final forward h (act warps own it)
    if (wid >= 12) {
        int off = net ? 256 : 0;
#pragma unroll
        for (int b = 0; b < NB; b++)
            d_hcat[(size_t)(b0 + b) * 512 + off + pt] = hreg[b];
    }
}

// ---- backward direction = ONE GRU step from h0=0 on x[:, T-1] --------------
__global__ __launch_bounds__(384) void bwd_kernel(
    const float* __restrict__ g_x, const float* __restrict__ a_x,
    const float* __restrict__ g_wib, const float* __restrict__ g_bib, const float* __restrict__ g_bhb,
    const float* __restrict__ a_wib, const float* __restrict__ a_bib, const float* __restrict__ a_bhb) {
    int bb0 = blockIdx.x * 8;
    int net = blockIdx.y;
    const float* x  = net ? a_x : g_x;
    int I           = net ? 64 : 63;
    const float* Wi = net ? a_wib : g_wib;
    const float* bi = net ? a_bib : g_bib;
    const float* bv = net ? a_bhb : g_bhb;

    __shared__ float xs[8][64];
    __shared__ float gsh[384][9];
    int j = threadIdx.x;  // 0..383

    for (int i = j; i < 512; i += 384) {
        int b = i >> 6, k = i & 63;
        xs[b][k] = (k < I) ? x[(size_t)(bb0 + b) * T * I + (size_t)(T - 1) * I + k] : 0.0f;
    }
    __syncthreads();

    {
        const float* wrow = Wi + (size_t)j * I;
        float acc[8];
        float bj = bi[j];
#pragma unroll
        for (int b = 0; b < 8; b++) acc[b] = bj;
        for (int k = 0; k < I; k++) {
            float w = wrow[k];
#pragma unroll
            for (int b = 0; b < 8; b++) acc[b] += w * xs[b][k];
        }
#pragma unroll
        for (int b = 0; b < 8; b++) gsh[j][b] = acc[b];
    }
    __syncthreads();

    if (j < 128) {
        int u = j;
        int off = net ? 256 : 0;
        float bvr = bv[u], bvz = bv[128 + u], bvn = bv[256 + u];
#pragma unroll
        for (int b = 0; b < 8; b++) {
            float r = sigmoidf_(gsh[u][b] + bvr);
            float z = sigmoidf_(gsh[128 + u][b] + bvz);
            float n = tanhf(gsh[256 + u][b] + r * bvn);
            d_hcat[(size_t)(bb0 + b) * 512 + off + 128 + u] = (1.0f - z) * n;
        }
    }
}

// ---- fusion MLP (512->256->128 relu) + heads (20, 30) ----------------------
__global__ __launch_bounds__(256) void mlp_kernel(
    const float* __restrict__ w1, const float* __restrict__ b1,
    const float* __restrict__ w2, const float* __restrict__ b2,
    const float* __restrict__ wm, const float* __restrict__ bm,
    const float* __restrict__ wa, const float* __restrict__ ba,
    float* __restrict__ out) {
    int b = blockIdx.x;
    __shared__ float hin[512];
    __shared__ float h1[256];
    __shared__ float h2[128];
    int t = threadIdx.x;
    hin[t]       = d_hcat[(size_t)b * 512 + t];
    hin[t + 256] = d_hcat[(size_t)b * 512 + 256 + t];
    __syncthreads();
    {
        float acc = b1[t];
        const float* wr = w1 + (size_t)t * 512;
#pragma unroll 8
        for (int k = 0; k < 512; k++) acc += wr[k] * hin[k];
        h1[t] = fmaxf(acc, 0.0f);
    }
    __syncthreads();
    if (t < 128) {
        float acc = b2[t];
        const float* wr = w2 + (size_t)t * 256;
#pragma unroll 8
        for (int k = 0; k < 256; k++) acc += wr[k] * h1[k];
        h2[t] = fmaxf(acc, 0.0f);
    }
    __syncthreads();
    if (t < 20) {
        float acc = bm[t];
        const float* wr = wm + (size_t)t * 128;
#pragma unroll 8
        for (int k = 0; k < 128; k++) acc += wr[k] * h2[k];
        out[(size_t)b * 20 + t] = acc;                       // lm
    } else if (t < 50) {
        int q = t - 20;
        float acc = ba[q];
        const float* wr = wa + (size_t)q * 128;
#pragma unroll 8
        for (int k = 0; k < 128; k++) acc += wr[k] * h2[k];
        out[5120 + (size_t)b * 30 + q] = acc;                // la (after 256*20 lm)
    }
}

extern "C" void kernel_launch(void* const* d_in, const int* in_sizes, int n_in,
                              void* d_out, int out_size) {
    const float* g_seq  = (const float*)d_in[0];
    const float* a_seq  = (const float*)d_in[1];
    const float* g_wif  = (const float*)d_in[2];
    const float* g_whf  = (const float*)d_in[3];
    const float* g_bif  = (const float*)d_in[4];
    const float* g_bhf  = (const float*)d_in[5];
    const float* g_wib  = (const float*)d_in[6];
    const float* g_bib  = (const float*)d_in[8];
    const float* g_bhb  = (const float*)d_in[9];
    const float* a_wif  = (const float*)d_in[10];
    const float* a_whf  = (const float*)d_in[11];
    const float* a_bif  = (const float*)d_in[12];
    const float* a_bhf  = (const float*)d_in[13];
    const float* a_wib  = (const float*)d_in[14];
    const float* a_bib  = (const float*)d_in[16];
    const float* a_bhb  = (const float*)d_in[17];
    const float* fuse_w1 = (const float*)d_in[18];
    const float* fuse_b1 = (const float*)d_in[19];
    const float* fuse_w2 = (const float*)d_in[20];
    const float* fuse_b2 = (const float*)d_in[21];
    const float* wm = (const float*)d_in[22];
    const float* bm = (const float*)d_in[23];
    const float* wa = (const float*)d_in[24];
    const float* ba = (const float*)d_in[25];

    const int rec_smem = 2304 + 2304 + 15360 + 30720 + 2048 + 49152;  // 101888
    cudaFuncSetAttribute(rec_fused_kernel, cudaFuncAttributeMaxDynamicSharedMemorySize, rec_smem);

    bwd_kernel<<<dim3(B / 8, 2), 384>>>(g_seq, a_seq, g_wib, g_bib, g_bhb, a_wib, a_bib, a_bhb);
    rec_fused_kernel<<<dim3(B / NB, 2), 512, rec_smem>>>(
        g_seq, a_seq, g_wif, g_bif, g_whf, g_bhf, a_wif, a_bif, a_whf, a_bhf);
    mlp_kernel<<<B, 256>>>(fuse_w1, fuse_b1, fuse_w2, fuse_b2, wm, bm, wa, ba, (float*)d_out);
}

// round 17
// speedup vs baseline: 1.2613x; 1.2613x over previous
#include <cuda_runtime.h>
#include <cuda_bf16.h>
#include <cuda_fp16.h>
#include <cstdint>

// ---------------------------------------------------------------------------
// EarlyFusionGRU: two biGRUs (B=256, T=512, H=128) + fusion MLP + 2 heads.
// Backward direction contributes only hb_seq[0] = ONE GRU step from h0=0 on
// x[:, T-1]. R17: gate-aligned m-tiles — each MMA warp owns the r, z, n rows
// of ONE jj block, so the activation runs in registers straight off the MMA
// accumulators: no Dsh exchange, ONE barrier per step. 384 threads
// (8 MMA warps + 4 copy warps), NB=4, 128 CTAs.
// ---------------------------------------------------------------------------

#define B 256
#define T 512
#define H 128
#define G3 384   // 3*H
#define BPITCH 136   // h B-tile row pitch
#define NB 4         // batches per CTA

static __device__ float d_hcat[(size_t)B * 512];      // [hg_f | hg_b | ha_f | ha_b]

__device__ __forceinline__ float sigmoidf_(float x) { return 1.0f / (1.0f + expf(-x)); }
__device__ __forceinline__ float tanh_ap(float x) {
    float y; asm("tanh.approx.f32 %0, %1;" : "=f"(y) : "f"(x)); return y;
}
__device__ __forceinline__ float sig_ap(float x) {
    return fmaf(tanh_ap(0.5f * x), 0.5f, 0.5f);
}
__device__ __forceinline__ uint32_t pkh2(float a, float b) {
    __half2 h = __floats2half2_rn(a, b);
    return *(uint32_t*)&h;
}
__device__ __forceinline__ void mma16816(float* c, const uint32_t* a, uint32_t b0, uint32_t b1) {
    asm volatile(
        "mma.sync.aligned.m16n8k16.row.col.f32.f16.f16.f32 "
        "{%0,%1,%2,%3}, {%4,%5,%6,%7}, {%8,%9}, {%0,%1,%2,%3};"
        : "+f"(c[0]), "+f"(c[1]), "+f"(c[2]), "+f"(c[3])
        : "r"(a[0]), "r"(a[1]), "r"(a[2]), "r"(a[3]), "r"(b0), "r"(b1));
}
__device__ __forceinline__ uint32_t smem_u32(const void* p) {
    uint32_t a; asm("{ .reg .u64 t; cvta.to.shared.u64 t, %1; cvt.u32.u64 %0, t; }" : "=r"(a) : "l"(p));
    return a;
}
__device__ __forceinline__ void cpasync4(uint32_t dst, const void* src) {
    asm volatile("cp.async.ca.shared.global [%0], [%1], 4;" :: "r"(dst), "l"(src));
}
#define CP_COMMIT() asm volatile("cp.async.commit_group;" ::: "memory")
#define CP_WAIT1()  asm volatile("cp.async.wait_group 1;" ::: "memory")
#define CP_WAIT0()  asm volatile("cp.async.wait_group 0;" ::: "memory")

// ---- fused recurrence, gate-aligned tiles, in-register activation ----------
__global__ __launch_bounds__(384, 1) void rec_fused_kernel(
    const float* __restrict__ g_x, const float* __restrict__ a_x,
    const float* __restrict__ g_wif, const float* __restrict__ g_bif,
    const float* __restrict__ g_whf, const float* __restrict__ g_bhf,
    const float* __restrict__ a_wif, const float* __restrict__ a_bif,
    const float* __restrict__ a_whf, const float* __restrict__ a_bhf) {
    int net = blockIdx.y;
    int b0 = blockIdx.x * NB;
    const float* x  = net ? a_x : g_x;
    int I           = net ? 64 : 63;
    const float* Wi = net ? a_wif : g_wif;
    const float* bi = net ? a_bif : g_bif;
    const float* Wh = net ? a_whf : g_whf;
    const float* bh = net ? a_bhf : g_bhf;

    int tid = threadIdx.x;
    int wid = tid >> 5;
    int lane = tid & 31;
    int qr = lane >> 2;
    int qc = lane & 3;

    // smem: Bh | Bx[2] | slab[2] | XFs ([12 quads][256 threads])
    extern __shared__ char dynsm[];
    __half (*Bh)[BPITCH] = (__half(*)[BPITCH])dynsm;                 // 2176 -> 2304
    __half (*Bx)[8][72]  = (__half(*)[8][72])(dynsm + 2304);         // 2304
    float* slab          = (float*)(dynsm + 4608);                   // 2048
    uint4* XFs           = (uint4*)(dynsm + 6656);                   // 49152
    uint32_t slab_u32 = smem_u32(slab);

    // ---- MMA warps (0-7): Wh fragments for 3 gate-aligned m-tiles ----------
    // Tile g covers rows g*128 + [16*wid, 16*wid+16).
    uint32_t A[3][8][4];
    if (wid < 8) {
#pragma unroll
        for (int g = 0; g < 3; g++) {
            int base = g * 128 + wid * 16;
            int r0 = base + qr, r1 = r0 + 8;
            const float2* w0p = (const float2*)(Wh + (size_t)r0 * 128);
            const float2* w1p = (const float2*)(Wh + (size_t)r1 * 128);
#pragma unroll
            for (int kb = 0; kb < 8; kb++) {
                int ci = kb * 8 + qc;
                float2 e00 = w0p[ci], e10 = w1p[ci];
                float2 e01 = w0p[ci + 4], e11 = w1p[ci + 4];
                A[g][kb][0] = pkh2(e00.x, e00.y);
                A[g][kb][1] = pkh2(e10.x, e10.y);
                A[g][kb][2] = pkh2(e01.x, e01.y);
                A[g][kb][3] = pkh2(e11.x, e11.y);
            }
            // Wi fragments -> SMEM private slots (12 quads per thread)
#pragma unroll
            for (int kx = 0; kx < 4; kx++) {
                int k0 = kx * 16 + qc * 2;
                uint32_t f[4];
#pragma unroll
                for (int r = 0; r < 2; r++) {
                    int ka = k0 + r * 8, kb2 = ka + 1;
                    float wa0 = (ka < I) ? Wi[(size_t)r0 * I + ka] : 0.0f;
                    float wa1 = (kb2 < I) ? Wi[(size_t)r0 * I + kb2] : 0.0f;
                    float wb0 = (ka < I) ? Wi[(size_t)r1 * I + ka] : 0.0f;
                    float wb1 = (kb2 < I) ? Wi[(size_t)r1 * I + kb2] : 0.0f;
                    f[0 + r * 2] = pkh2(wa0, wa1);
                    f[1 + r * 2] = pkh2(wb0, wb1);
                }
                XFs[(g * 4 + kx) * 256 + tid] = make_uint4(f[0], f[1], f[2], f[3]);
            }
        }
    }

    // zero B-tiles (h0 = 0; batch rows NB..7 and pad cols stay zero forever)
    for (int i = tid; i < 8 * BPITCH; i += 384)
        ((__half*)Bh)[i] = __float2half_rn(0.0f);
    for (int i = tid; i < 2 * 8 * 72; i += 384)
        ((__half*)Bx)[i] = __float2half_rn(0.0f);

    // ---- per-thread activation constants (MMA warps, qc<2 active) ----------
    int jj0 = wid * 16 + qr, jj1 = jj0 + 8;   // the two gate rows this thread owns
    float brz_r0 = 0.f, brz_r1 = 0.f, brz_z0 = 0.f, brz_z1 = 0.f;
    float bin0 = 0.f, bin1 = 0.f, bhn0 = 0.f, bhn1 = 0.f;
    if (wid < 8) {
        brz_r0 = bi[jj0] + bh[jj0];           brz_r1 = bi[jj1] + bh[jj1];
        brz_z0 = bi[128 + jj0] + bh[128 + jj0]; brz_z1 = bi[128 + jj1] + bh[128 + jj1];
        bin0 = bi[256 + jj0]; bin1 = bi[256 + jj1];
        bhn0 = bh[256 + jj0]; bhn1 = bh[256 + jj1];
    }
    float hv[4];   // h for (jj0,b0q), (jj0,b0q+1), (jj1,b0q), (jj1,b0q+1)
#pragma unroll
    for (int e = 0; e < 4; e++) hv[e] = 0.0f;
    int bq = 2 * qc;               // first batch column this thread holds

    // ---- copy-warp prologue (warps 8-11): slabs + Bx[0] --------------------
    if (wid >= 8) {
        int ct = tid - 256;  // 0..127
#pragma unroll 1
        for (int tt = 0; tt < 2; tt++) {
            for (int i = ct; i < 256; i += 128) {
                int b = i >> 6, k = i & 63;
                if (k < I)
                    cpasync4(slab_u32 + (tt * 256 + i) * 4,
                             x + (size_t)(b0 + b) * (T * I) + (size_t)tt * I + k);
            }
            CP_COMMIT();
        }
        CP_WAIT1();   // slab[0] = x(0) resident
        for (int i = ct; i < 256; i += 128) {
            int r = i >> 6, k = i & 63;
            float v = (k < I) ? slab[r * 64 + k] : 0.0f;
            Bx[0][r][k] = __float2half_rn(v);
        }
    }
    __syncthreads();

    const __half* BhF = &Bh[0][0];

#pragma unroll 1
    for (int t = 0; t < T; t++) {
        if (wid < 8) {
            // ---- MMAs: 3 gate tiles x (8 h-ksteps + 4 x-ksteps) -------------
            float cg[3][4], cx[4];
#pragma unroll
            for (int g = 0; g < 3; g++)
#pragma unroll
                for (int r = 0; r < 4; r++) cg[g][r] = 0.0f;
#pragma unroll
            for (int r = 0; r < 4; r++) cx[r] = 0.0f;

#pragma unroll
            for (int kb = 0; kb < 8; kb++) {
                int koff = qr * BPITCH + kb * 16 + qc * 2;
                uint32_t bf0 = *(const uint32_t*)(BhF + koff);
                uint32_t bf1 = *(const uint32_t*)(BhF + koff + 8);
#pragma unroll
                for (int g = 0; g < 3; g++)
                    mma16816(cg[g], A[g][kb], bf0, bf1);
            }
            const __half* BxF = &Bx[t & 1][0][0];
#pragma unroll
            for (int kx = 0; kx < 4; kx++) {
                int koff = qr * 72 + kx * 16 + qc * 2;
                uint32_t bf0 = *(const uint32_t*)(BxF + koff);
                uint32_t bf1 = *(const uint32_t*)(BxF + koff + 8);
                uint4 f0 = XFs[(0 * 4 + kx) * 256 + tid];
                uint32_t a0[4] = {f0.x, f0.y, f0.z, f0.w};
                mma16816(cg[0], a0, bf0, bf1);        // r gate: x folded in
                uint4 f1 = XFs[(1 * 4 + kx) * 256 + tid];
                uint32_t a1[4] = {f1.x, f1.y, f1.z, f1.w};
                mma16816(cg[1], a1, bf0, bf1);        // z gate: x folded in
                uint4 f2 = XFs[(2 * 4 + kx) * 256 + tid];
                uint32_t a2[4] = {f2.x, f2.y, f2.z, f2.w};
                mma16816(cx, a2, bf0, bf1);           // n gate: x kept separate
            }

            // ---- in-register activation (batches bq, bq+1 valid iff qc<2) ---
            if (qc < 2) {
                // e0: (jj0, bq)   e1: (jj0, bq+1)   e2: (jj1, bq)  e3: (jj1, bq+1)
                float r0 = sig_ap(cg[0][0] + brz_r0);
                float r1 = sig_ap(cg[0][1] + brz_r0);
                float r2 = sig_ap(cg[0][2] + brz_r1);
                float r3 = sig_ap(cg[0][3] + brz_r1);
                float z0 = sig_ap(cg[1][0] + brz_z0);
                float z1 = sig_ap(cg[1][1] + brz_z0);
                float z2 = sig_ap(cg[1][2] + brz_z1);
                float z3 = sig_ap(cg[1][3] + brz_z1);
                float n0 = tanh_ap(cx[0] + bin0 + r0 * (cg[2][0] + bhn0));
                float n1 = tanh_ap(cx[1] + bin0 + r1 * (cg[2][1] + bhn0));
                float n2 = tanh_ap(cx[2] + bin1 + r2 * (cg[2][2] + bhn1));
                float n3 = tanh_ap(cx[3] + bin1 + r3 * (cg[2][3] + bhn1));
                hv[0] = n0 + z0 * (hv[0] - n0);
                hv[1] = n1 + z1 * (hv[1] - n1);
                hv[2] = n2 + z2 * (hv[2] - n2);
                hv[3] = n3 + z3 * (hv[3] - n3);
                Bh[bq][jj0]     = __float2half_rn(hv[0]);
                Bh[bq + 1][jj0] = __float2half_rn(hv[1]);
                Bh[bq][jj1]     = __float2half_rn(hv[2]);
                Bh[bq + 1][jj1] = __float2half_rn(hv[3]);
            }
        } else {
            // ---- copy warps: convert Bx[(t+1)&1] <- x(t+1); stage x(t+2) ----
            int ct = tid - 256;
            if (t + 1 < T) {
                CP_WAIT0();   // slab[(t+1)&1] = x(t+1) resident
                int nb = (t + 1) & 1;
                for (int i = ct; i < 256; i += 128) {
                    int r = i >> 6, k = i & 63;
                    float v = (k < I) ? slab[nb * 256 + r * 64 + k] : 0.0f;
                    Bx[nb][r][k] = __float2half_rn(v);
                }
                if (t + 2 < T) {
                    uint32_t dst = slab_u32 + ((t & 1) * 256) * 4;
                    for (int i = ct; i < 256; i += 128) {
                        int b = i >> 6, k = i & 63;
                        if (k < I)
                            cpasync4(dst + i * 4,
                                     x + (size_t)(b0 + b) * (T * I) + (size_t)(t + 2) * I + k);
                    }
                    CP_COMMIT();
                }
            }
        }
        __syncthreads();   // Bh(t+1) + Bx[(t+1)&1] ready for next step
    }

    // ---- write final forward h ---------------------------------------------
    if (wid < 8 && qc < 2) {
        int off = net ? 256 : 0;
        d_hcat[(size_t)(b0 + bq) * 512 + off + jj0]     = hv[0];
        d_hcat[(size_t)(b0 + bq + 1) * 512 + off + jj0] = hv[1];
        d_hcat[(size_t)(b0 + bq) * 512 + off + jj1]     = hv[2];
        d_hcat[(size_t)(b0 + bq + 1) * 512 + off + jj1] = hv[3];
    }
}

// ---- backward direction = ONE GRU step from h0=0 on x[:, T-1] --------------
__global__ __launch_bounds__(384) void bwd_kernel(
    const float* __restrict__ g_x, const float* __restrict__ a_x,
    const float* __restrict__ g_wib, const float* __restrict__ g_bib, const float* __restrict__ g_bhb,
    const float* __restrict__ a_wib, const float* __restrict__ a_bib, const float* __restrict__ a_bhb) {
    int bb0 = blockIdx.x * 8;
    int net = blockIdx.y;
    const float* x  = net ? a_x : g_x;
    int I           = net ? 64 : 63;
    const float* Wi = net ? a_wib : g_wib;
    const float* bi = net ? a_bib : g_bib;
    const float* bv = net ? a_bhb : g_bhb;

    __shared__ float xs[8][64];
    __shared__ float gsh[384][9];
    int j = threadIdx.x;  // 0..383

    for (int i = j; i < 512; i += 384) {
        int b = i >> 6, k = i & 63;
        xs[b][k] = (k < I) ? x[(size_t)(bb0 + b) * T * I + (size_t)(T - 1) * I + k] : 0.0f;
    }
    __syncthreads();

    {
        const float* wrow = Wi + (size_t)j * I;
        float acc[8];
        float bj = bi[j];
#pragma unroll
        for (int b = 0; b < 8; b++) acc[b] = bj;
        for (int k = 0; k < I; k++) {
            float w = wrow[k];
#pragma unroll
            for (int b = 0; b < 8; b++) acc[b] += w * xs[b][k];
        }
#pragma unroll
        for (int b = 0; b < 8; b++) gsh[j][b] = acc[b];
    }
    __syncthreads();

    if (j < 128) {
        int u = j;
        int off = net ? 256 : 0;
        float bvr = bv[u], bvz = bv[128 + u], bvn = bv[256 + u];
#pragma unroll
        for (int b = 0; b < 8; b++) {
            float r = sigmoidf_(gsh[u][b] + bvr);
            float z = sigmoidf_(gsh[128 + u][b] + bvz);
            float n = tanhf(gsh[256 + u][b] + r * bvn);
            d_hcat[(size_t)(bb0 + b) * 512 + off + 128 + u] = (1.0f - z) * n;
        }
    }
}

// ---- fusion MLP (512->256->128 relu) + heads (20, 30) ----------------------
__global__ __launch_bounds__(256) void mlp_kernel(
    const float* __restrict__ w1, const float* __restrict__ b1,
    const float* __restrict__ w2, const float* __restrict__ b2,
    const float* __restrict__ wm, const float* __restrict__ bm,
    const float* __restrict__ wa, const float* __restrict__ ba,
    float* __restrict__ out) {
    int b = blockIdx.x;
    __shared__ float hin[512];
    __shared__ float h1[256];
    __shared__ float h2[128];
    int t = threadIdx.x;
    hin[t]       = d_hcat[(size_t)b * 512 + t];
    hin[t + 256] = d_hcat[(size_t)b * 512 + 256 + t];
    __syncthreads();
    {
        float acc = b1[t];
        const float* wr = w1 + (size_t)t * 512;
#pragma unroll 8
        for (int k = 0; k < 512; k++) acc += wr[k] * hin[k];
        h1[t] = fmaxf(acc, 0.0f);
    }
    __syncthreads();
    if (t < 128) {
        float acc = b2[t];
        const float* wr = w2 + (size_t)t * 256;
#pragma unroll 8
        for (int k = 0; k < 256; k++) acc += wr[k] * h1[k];
        h2[t] = fmaxf(acc, 0.0f);
    }
    __syncthreads();
    if (t < 20) {
        float acc = bm[t];
        const float* wr = wm + (size_t)t * 128;
#pragma unroll 8
        for (int k = 0; k < 128; k++) acc += wr[k] * h2[k];
        out[(size_t)b * 20 + t] = acc;                       // lm
    } else if (t < 50) {
        int q = t - 20;
        float acc = ba[q];
        const float* wr = wa + (size_t)q * 128;
#pragma unroll 8
        for (int k = 0; k < 128; k++) acc += wr[k] * h2[k];
        out[5120 + (size_t)b * 30 + q] = acc;                // la (after 256*20 lm)
    }
}

extern "C" void kernel_launch(void* const* d_in, const int* in_sizes, int n_in,
                              void* d_out, int out_size) {
    const float* g_seq  = (const float*)d_in[0];
    const float* a_seq  = (const float*)d_in[1];
    const float* g_wif  = (const float*)d_in[2];
    const float* g_whf  = (const float*)d_in[3];
    const float* g_bif  = (const float*)d_in[4];
    const float* g_bhf  = (const float*)d_in[5];
    const float* g_wib  = (const float*)d_in[6];
    const float* g_bib  = (const float*)d_in[8];
    const float* g_bhb  = (const float*)d_in[9];
    const float* a_wif  = (const float*)d_in[10];
    const float* a_whf  = (const float*)d_in[11];
    const float* a_bif  = (const float*)d_in[12];
    const float* a_bhf  = (const float*)d_in[13];
    const float* a_wib  = (const float*)d_in[14];
    const float* a_bib  = (const float*)d_in[16];
    const float* a_bhb  = (const float*)d_in[17];
    const float* fuse_w1 = (const float*)d_in[18];
    const float* fuse_b1 = (const float*)d_in[19];
    const float* fuse_w2 = (const float*)d_in[20];
    const float* fuse_b2 = (const float*)d_in[21];
    const float* wm = (const float*)d_in[22];
    const float* bm = (const float*)d_in[23];
    const float* wa = (const float*)d_in[24];
    const float* ba = (const float*)d_in[25];

    const int rec_smem = 2304 + 2304 + 2048 + 49152;   // Bh | Bx | slab | XFs = 55808
    cudaFuncSetAttribute(rec_fused_kernel, cudaFuncAttributeMaxDynamicSharedMemorySize, rec_smem);

    bwd_kernel<<<dim3(B / 8, 2), 384>>>(g_seq, a_seq, g_wib, g_bib, g_bhb, a_wib, a_bib, a_bhb);
    rec_fused_kernel<<<dim3(B / NB, 2), 384, rec_smem>>>(
        g_seq, a_seq, g_wif, g_bif, g_whf, g_bhf, a_wif, a_bif, a_whf, a_bhf);
    mlp_kernel<<<B, 256>>>(fuse_w1, fuse_b1, fuse_w2, fuse_b2, wm, bm, wa, ba, (float*)d_out);
}